// round 1
// baseline (speedup 1.0000x reference)
#include <cuda_runtime.h>
#include <cuda_bf16.h>

#define Wd 1024
#define Hd 1024
#define Bd 4
#define Cd 4
#define HWd (Wd * Hd)

// Scratch (device globals — no dynamic allocation allowed).
__device__ float4 g_P1[Bd * HWd];   // packed img channels        (64 MB)
__device__ float2 g_P2[Bd * HWd];   // (alpha, signed CoC radius) (32 MB)
__device__ float4 g_smp[512];       // (xs, ys, norm, 0) compacted aperture samples
__device__ int    g_cnt;

// ---------------------------------------------------------------------------
// Build the compacted aperture-sample table. Values -1 + i*(2/(n-1)) are exact
// fp32 for n=17, so the X^2+Y^2 <= 1 mask matches the numpy reference exactly.
// ---------------------------------------------------------------------------
__global__ void prep_samples_kernel(const int* spc_ptr) {
    int n = 17;
    if (spc_ptr) {
        int v = spc_ptr[0];          // works for int32, and for little-endian int64 too
        if (v >= 2 && v <= 512) n = v;
    }
    float step = 2.0f / (float)(n - 1);
    int c = 0;
    for (int i = 0; i < n; i++) {
        float xs = -1.0f + (float)i * step;
        for (int j = 0; j < n; j++) {
            float ys = -1.0f + (float)j * step;
            float d2 = xs * xs + ys * ys;
            if (d2 <= 1.0f) {
                g_smp[c] = make_float4(xs, ys, sqrtf(d2), 0.0f);
                c++;
            }
        }
    }
    g_cnt = c;
}

// ---------------------------------------------------------------------------
// Pack per-pixel data: P1 = img rgba, P2 = (alpha, r) with r = K*(coff - df).
// ---------------------------------------------------------------------------
__global__ __launch_bounds__(256)
void prep_pack_kernel(const float* __restrict__ img,
                      const float* __restrict__ alpha,
                      const float* __restrict__ coff,
                      const float* __restrict__ K,
                      const float* __restrict__ df) {
    int p = blockIdx.x * blockDim.x + threadIdx.x;
    int b = blockIdx.y;
    if (p >= HWd) return;
    size_t ib = (size_t)b * Cd * HWd;
    int    base = b * HWd;
    float4 v;
    v.x = img[ib + 0 * HWd + p];
    v.y = img[ib + 1 * HWd + p];
    v.z = img[ib + 2 * HWd + p];
    v.w = img[ib + 3 * HWd + p];
    g_P1[base + p] = v;
    float r = K[b] * (coff[base + p] - df[b]);
    g_P2[base + p] = make_float2(alpha[base + p], r);
}

// ---------------------------------------------------------------------------
// Main render: one thread per output pixel, loop over compacted samples.
// ---------------------------------------------------------------------------
__global__ __launch_bounds__(256)
void render_kernel(const float* __restrict__ Eta, float* __restrict__ out) {
    __shared__ float4 s_smp[512];
    __shared__ int    s_cnt;

    int tid = threadIdx.y * 32 + threadIdx.x;
    if (tid == 0) s_cnt = g_cnt;
    #pragma unroll
    for (int k = tid; k < 512; k += 256) s_smp[k] = g_smp[k];
    __syncthreads();
    int cnt = s_cnt;

    int x = blockIdx.x * 32 + threadIdx.x;
    int y = blockIdx.y * 8  + threadIdx.y;
    int b = blockIdx.z;
    int p = y * Wd + x;
    int base = b * HWd;

    float eta  = __ldg(&Eta[b]);
    float2 c2  = __ldg(&g_P2[base + p]);
    float r    = c2.y;
    float rabs = fabsf(r);
    float px = (float)x, py = (float)y;

    float4 acc  = make_float4(0.f, 0.f, 0.f, 0.f);
    float  accw = 0.0f;

    for (int k = 0; k < cnt; k++) {
        float4 s  = s_smp[k];                       // xs, ys, norm
        float fx  = fmaf(r, s.x, px);
        float fy  = fmaf(r, s.y, py);
        int sx = min(max(__float2int_rn(fx), 0), Wd - 1);   // rn == round-half-even == jnp.round
        int sy = min(max(__float2int_rn(fy), 0), Hd - 1);
        int idx = base + (sy << 10) + sx;

        float4 q  = __ldg(&g_P1[idx]);
        float2 ar = __ldg(&g_P2[idx]);

        float rq   = fabsf(ar.y);
        float dist = rabs * s.z;
        float t    = fmaf(eta, rq - dist, 1.0f);
        float e    = __expf(-t);                    // sigmoid(t) = 1/(1+e)
        float denom = (1.0f + e) * fmaf(3.14159265358979323846f * rq, rq, 1.0f);
        float w    = __fdividef(ar.x, denom);       // a_q * sigmoid / (pi r^2 + 1), one RCP

        acc.x = fmaf(w, q.x, acc.x);
        acc.y = fmaf(w, q.y, acc.y);
        acc.z = fmaf(w, q.z, acc.z);
        acc.w = fmaf(w, q.w, acc.w);
        accw += w;
    }

    size_t ob = (size_t)b * Cd * HWd;
    out[ob + 0 * HWd + p] = acc.x;
    out[ob + 1 * HWd + p] = acc.y;
    out[ob + 2 * HWd + p] = acc.z;
    out[ob + 3 * HWd + p] = acc.w;
    out[(size_t)Bd * Cd * HWd + (size_t)b * HWd + p] = accw;
}

// ---------------------------------------------------------------------------
extern "C" void kernel_launch(void* const* d_in, const int* in_sizes, int n_in,
                              void* d_out, int out_size) {
    const float* images = (const float*)d_in[0];   // [B,1,4,H,W]
    const float* alphas = (const float*)d_in[1];   // [B,1,1,H,W]
    const float* coffs  = (const float*)d_in[2];   // [B,1,1,H,W]
    const float* K      = (const float*)d_in[3];   // [B]
    const float* df     = (const float*)d_in[4];   // [B]
    const float* eta    = (const float*)d_in[5];   // [B]
    const int*   spc    = (n_in >= 7) ? (const int*)d_in[6] : nullptr;
    float* out = (float*)d_out;

    prep_samples_kernel<<<1, 1>>>(spc);

    dim3 pb(256, 1, 1);
    dim3 pg((HWd + 255) / 256, Bd, 1);
    prep_pack_kernel<<<pg, pb>>>(images, alphas, coffs, K, df);

    dim3 rb(32, 8, 1);
    dim3 rg(Wd / 32, Hd / 8, Bd);
    render_kernel<<<rg, rb>>>(eta, out);
}

// round 2
// speedup vs baseline: 1.5013x; 1.5013x over previous
#include <cuda_runtime.h>
#include <cuda_fp16.h>

#define Wd 1024
#define Hd 1024
#define Bd 4
#define Cd 4
#define HWd (Wd * Hd)
#define PI_F 3.14159265358979323846f

// One 16B record per pixel: {img as 4x half, A = alpha/(pi r^2 + 1), E = eta*r}
__device__ float4 g_R[Bd * HWd];    // 64 MB scratch
__device__ float4 g_smp[512];       // compacted aperture samples (xs, ys, norm, 0)
__device__ int    g_cnt;

// ---------------------------------------------------------------------------
// Pack kernel: builds per-pixel records. Block (0,0)'s first warp additionally
// builds the compacted aperture-sample table (deterministic ballot compaction,
// row-major (i,j) order matching numpy's meshgrid mask).
// ---------------------------------------------------------------------------
__global__ __launch_bounds__(256)
void prep_pack_kernel(const float* __restrict__ img,
                      const float* __restrict__ alpha,
                      const float* __restrict__ coff,
                      const float* __restrict__ K,
                      const float* __restrict__ df,
                      const float* __restrict__ eta,
                      const int*   __restrict__ spc) {
    if (blockIdx.x == 0 && blockIdx.y == 0 && threadIdx.x < 32) {
        int n = 17;
        if (spc) { int v = spc[0]; if (v >= 2 && v <= 512) n = v; }
        float step = 2.0f / (float)(n - 1);
        int total = n * n;
        int c = 0;
        for (int base = 0; base < total; base += 32) {
            int id = base + (int)threadIdx.x;
            int i = id / n, j = id - i * n;
            float xs = -1.0f + (float)i * step;
            float ys = -1.0f + (float)j * step;
            float d2 = xs * xs + ys * ys;
            bool pred = (id < total) && (d2 <= 1.0f);
            unsigned m = __ballot_sync(0xffffffffu, pred);
            if (pred) {
                int off = c + __popc(m & ((1u << threadIdx.x) - 1u));
                g_smp[off] = make_float4(xs, ys, sqrtf(d2), 0.0f);
            }
            c += __popc(m);
        }
        if (threadIdx.x == 0) g_cnt = c;
    }

    int p = blockIdx.x * blockDim.x + threadIdx.x;
    int b = blockIdx.y;
    if (p >= HWd) return;
    size_t ib = (size_t)b * Cd * HWd;
    int base = b * HWd;

    float i0 = img[ib + 0 * HWd + p];
    float i1 = img[ib + 1 * HWd + p];
    float i2 = img[ib + 2 * HWd + p];
    float i3 = img[ib + 3 * HWd + p];

    float r  = K[b] * (coff[base + p] - df[b]);
    float ra = fabsf(r);
    float denom = (PI_F * ra) * ra + 1.0f;
    float A = alpha[base + p] / denom;
    float E = eta[b] * r;

    __half2 h01 = __floats2half2_rn(i0, i1);
    __half2 h23 = __floats2half2_rn(i2, i3);
    float4 rec;
    rec.x = __uint_as_float(*reinterpret_cast<unsigned*>(&h01));
    rec.y = __uint_as_float(*reinterpret_cast<unsigned*>(&h23));
    rec.z = A;
    rec.w = E;
    g_R[base + p] = rec;
}

// ---------------------------------------------------------------------------
// Render: one thread per output pixel; one LDG.128 gather per aperture sample.
// ---------------------------------------------------------------------------
__global__ __launch_bounds__(256)
void render_kernel(const float* __restrict__ coff,
                   const float* __restrict__ K,
                   const float* __restrict__ df,
                   const float* __restrict__ Eta,
                   float* __restrict__ out) {
    __shared__ float4 s_smp[512];
    __shared__ int    s_cnt;

    int tid = threadIdx.y * 32 + threadIdx.x;
    if (tid == 0) s_cnt = g_cnt;
    #pragma unroll
    for (int k = tid; k < 512; k += 256) s_smp[k] = g_smp[k];
    __syncthreads();
    int cnt = s_cnt;

    int x = blockIdx.x * 32 + threadIdx.x;
    int y = blockIdx.y * 8  + threadIdx.y;
    int b = blockIdx.z;
    int p = y * Wd + x;
    int base = b * HWd;

    // exact signed CoC radius for this pixel (same expression as pack kernel)
    float r   = __ldg(&K[b]) * (__ldg(&coff[base + p]) - __ldg(&df[b]));
    float eE  = __ldg(&Eta[b]) * fabsf(r);   // eta * |r|
    float px = (float)x, py = (float)y;

    const float4* __restrict__ pb = g_R + base;

    float a0 = 0.f, a1 = 0.f, a2 = 0.f, a3 = 0.f, aw = 0.f;

    #pragma unroll 4
    for (int k = 0; k < cnt; k++) {
        float4 s = s_smp[k];
        float fx = fmaf(r, s.x, px);
        float fy = fmaf(r, s.y, py);
        int sx = min(max(__float2int_rn(fx), 0), Wd - 1);
        int sy = min(max(__float2int_rn(fy), 0), Hd - 1);
        int idx = (sy << 10) + sx;

        float4 rv = __ldg(pb + idx);        // {half4 img, A, E}

        float d = fmaf(-eE, s.z, 1.0f);     // 1 - eta*|r|*||s||
        float t = fabsf(rv.w) + d;          // eta*|r_q| + 1 - eta*|r|*||s||
        float e = __expf(-t);
        float w = rv.z * __frcp_rn(1.0f + e);  // A_q * sigmoid(t)

        unsigned u01 = __float_as_uint(rv.x);
        unsigned u23 = __float_as_uint(rv.y);
        float2 f01 = __half22float2(*reinterpret_cast<__half2*>(&u01));
        float2 f23 = __half22float2(*reinterpret_cast<__half2*>(&u23));

        a0 = fmaf(w, f01.x, a0);
        a1 = fmaf(w, f01.y, a1);
        a2 = fmaf(w, f23.x, a2);
        a3 = fmaf(w, f23.y, a3);
        aw += w;
    }

    size_t ob = (size_t)b * Cd * HWd;
    out[ob + 0 * HWd + p] = a0;
    out[ob + 1 * HWd + p] = a1;
    out[ob + 2 * HWd + p] = a2;
    out[ob + 3 * HWd + p] = a3;
    out[(size_t)Bd * Cd * HWd + (size_t)b * HWd + p] = aw;
}

// ---------------------------------------------------------------------------
extern "C" void kernel_launch(void* const* d_in, const int* in_sizes, int n_in,
                              void* d_out, int out_size) {
    const float* images = (const float*)d_in[0];
    const float* alphas = (const float*)d_in[1];
    const float* coffs  = (const float*)d_in[2];
    const float* K      = (const float*)d_in[3];
    const float* df     = (const float*)d_in[4];
    const float* eta    = (const float*)d_in[5];
    const int*   spc    = (n_in >= 7) ? (const int*)d_in[6] : nullptr;
    float* out = (float*)d_out;

    dim3 pb(256, 1, 1);
    dim3 pg((HWd + 255) / 256, Bd, 1);
    prep_pack_kernel<<<pg, pb>>>(images, alphas, coffs, K, df, eta, spc);

    dim3 rb(32, 8, 1);
    dim3 rg(Wd / 32, Hd / 8, Bd);
    render_kernel<<<rg, rb>>>(coffs, K, df, eta, out);
}